// round 9
// baseline (speedup 1.0000x reference)
#include <cuda_runtime.h>
#include <cuda_fp16.h>
#include <cstdint>

// Problem constants (fixed by the reference: B=4, N=4096, C=256)
#define BB 4
#define NN 4096
#define CC 256
#define M_TOT (BB * NN)          // 16384 rows
#define LN_EPS 1e-6f

// ---------------------------------------------------------------------------
// Scratch (static device globals; no runtime allocation allowed)
// ---------------------------------------------------------------------------
__device__ __align__(16) __half g_BT[CC * CC];   // [n][k] = fp16(Wvo[k][n])
__device__ __align__(16) __half g_zh[(size_t)M_TOT * CC]; // pre-LN activations (8.4 MB, fp16)
__device__ float g_psum[256 * CC];               // per-(64-row warp-tile) col sums
__device__ float g_psq [256 * CC];
__device__ __align__(16) float g_ivsc[BB * CC];  // rsqrt(var+eps) * ln_scale
__device__ __align__(16) float g_bb[BB * CC];    // ln_bias - mean * ivsc

// ---------------------------------------------------------------------------
// Warp-MMA + cp.async helpers (sm_80-era PTX: compiles at compute_103)
// ---------------------------------------------------------------------------
__device__ __forceinline__ uint32_t smem_u32(const void* p) {
    uint32_t a;
    asm("{ .reg .u64 t; cvta.to.shared.u64 t, %1; cvt.u32.u64 %0, t; }" : "=r"(a) : "l"(p));
    return a;
}
#define LDMX4(r, a) \
    asm volatile("ldmatrix.sync.aligned.m8n8.x4.shared.b16 {%0,%1,%2,%3}, [%4];" \
        : "=r"((r)[0]), "=r"((r)[1]), "=r"((r)[2]), "=r"((r)[3]) : "r"(a))
#define LDMX2(r, a) \
    asm volatile("ldmatrix.sync.aligned.m8n8.x2.shared.b16 {%0,%1}, [%2];" \
        : "=r"((r)[0]), "=r"((r)[1]) : "r"(a))
#define MMA16816H(c, a, b) \
    asm volatile("mma.sync.aligned.m16n8k16.row.col.f32.f16.f16.f32 " \
        "{%0,%1,%2,%3}, {%4,%5,%6,%7}, {%8,%9}, {%0,%1,%2,%3};" \
        : "+f"((c)[0]), "+f"((c)[1]), "+f"((c)[2]), "+f"((c)[3]) \
        : "r"((a)[0]), "r"((a)[1]), "r"((a)[2]), "r"((a)[3]), "r"((b)[0]), "r"((b)[1]))
#define CP16(dst, src) \
    asm volatile("cp.async.cg.shared.global [%0], [%1], 16;" :: "r"(dst), "l"(src))
#define CP_COMMIT() asm volatile("cp.async.commit_group;" ::: "memory")
#define CP_WAIT(n)  asm volatile("cp.async.wait_group %0;" :: "n"(n) : "memory")

// Convert 8 fp32 -> 8 fp16 packed as uint4.
__device__ __forceinline__ uint4 cvt8h(float4 a, float4 b) {
    float f[8] = {a.x, a.y, a.z, a.w, b.x, b.y, b.z, b.w};
    uint32_t h[8];
#pragma unroll
    for (int j = 0; j < 8; ++j)
        h[j] = (uint32_t)__half_as_ushort(__float2half_rn(f[j]));
    return make_uint4(h[0] | (h[1] << 16), h[2] | (h[3] << 16),
                      h[4] | (h[5] << 16), h[6] | (h[7] << 16));
}

// ---------------------------------------------------------------------------
// Kernel 1: fold weights Wvo = Wv @ Wo -> fp16, store TRANSPOSED [n][k]
// (col-major B operand for mma.row.col). Biases cancel in the points-axis
// LayerNorm and are dead.
// ---------------------------------------------------------------------------
__global__ void k_prep(const float* __restrict__ Wv, const float* __restrict__ Wo) {
    const int i = blockIdx.x;     // k index (row of Wvo)
    const int j = threadIdx.x;    // n index (col of Wvo)
    float acc = 0.f;
#pragma unroll 8
    for (int m = 0; m < CC; ++m)
        acc += Wv[i * CC + m] * Wo[m * CC + j];
    g_BT[j * CC + i] = __float2half_rn(acc);
}

// ---------------------------------------------------------------------------
// Kernel 2: fp16 warp-MMA GEMM  z = X[16384,256] @ Wvo[256,256]
// 128 CTAs x 256 thr; CTA tile 128m x 256n; warp tile 64x64; fp32 accum.
// K in 4 chunks of 64, double-buffered (B cp.async, A reg-prefetch + cvt).
// z stored fp16. Fused deterministic per-warp column stats (from fp32 frags).
// smem = 2 stages x (A 16K + B 32K) = 96 KB.
// ---------------------------------------------------------------------------
#define SM_A(s) ((s) * 49152)
#define SM_B(s) ((s) * 49152 + 16384)
#define SMEM_TOTAL 98304

__global__ void __launch_bounds__(256, 1)
k_gemm_mma(const float* __restrict__ X) {
    extern __shared__ char smem[];
    const uint32_t sb = smem_u32(smem);
    const int tid = threadIdx.x;
    const int lane = tid & 31;
    const int warp = tid >> 5;
    const int warp_m = warp & 1;       // 2 warps along m (64 each)
    const int warp_n = warp >> 1;      // 4 warps along n (64 each)
    const int rowBase = blockIdx.x * 128;

    // A-load mapping: 2 threads per row, 32 fp32 each (8 float4)
    const int a_ldrow = tid >> 1;
    const int a_ldch  = (tid & 1) * 32;

    float c[4][8][4];
#pragma unroll
    for (int mi = 0; mi < 4; ++mi)
#pragma unroll
        for (int ni = 0; ni < 8; ++ni)
#pragma unroll
            for (int e = 0; e < 4; ++e) c[mi][ni][e] = 0.f;

    auto loadB = [&](int stage, int kc) {
        const char* bp = (const char*)g_BT + (size_t)tid * 512 + kc * 128;
        const uint32_t rsw = ((uint32_t)(tid & 7)) << 4;
#pragma unroll
        for (int g = 0; g < 8; ++g) {
            uint32_t sw = ((uint32_t)(tid * 128 + g * 16)) ^ rsw;
            CP16(sb + SM_B(stage) + sw, bp + g * 16);
        }
        CP_COMMIT();
    };
    auto loadAreg = [&](int kc, float4* xr) {
        const float4* xp = (const float4*)(X + (size_t)(rowBase + a_ldrow) * CC + kc * 64 + a_ldch);
#pragma unroll
        for (int g = 0; g < 8; ++g) xr[g] = xp[g];
    };
    auto cvtA = [&](int stage, const float4* xr) {
        const uint32_t rsw = ((uint32_t)(a_ldrow & 7)) << 4;
#pragma unroll
        for (int g = 0; g < 4; ++g) {
            uint4 hv = cvt8h(xr[2 * g], xr[2 * g + 1]);
            uint32_t sw = ((uint32_t)(a_ldrow * 128 + (a_ldch + g * 8) * 2)) ^ rsw;
            *(uint4*)(smem + SM_A(stage) + sw) = hv;
        }
    };

    // ---- prologue: B0,B1 in flight; A0 converted to smem; A1 in regs ----
    float4 xr[8];
    loadB(0, 0);
    loadB(1, 1);
    loadAreg(0, xr);
    cvtA(0, xr);
    loadAreg(1, xr);
    CP_WAIT(1);            // B0 arrived
    __syncthreads();

    // ldmatrix address components
    const int arow = warp_m * 64 + (lane & 15);
    const uint32_t acb = (uint32_t)((lane >> 4) << 4);
    const int brow0 = warp_n * 64 + (lane & 7);
    const uint32_t bcb = (uint32_t)(((lane >> 3) & 1) << 4);

#pragma unroll
    for (int kc = 0; kc < 4; ++kc) {
        const int s = kc & 1;
        const uint32_t AS = sb + SM_A(s);
        const uint32_t BS = sb + SM_B(s);

#pragma unroll
        for (int ks = 0; ks < 4; ++ks) {
            const uint32_t kbyte = (uint32_t)(ks * 32);
            uint32_t a[4][4];
#pragma unroll
            for (int mi = 0; mi < 4; ++mi) {
                const int r = arow + mi * 16;
                uint32_t sw = ((uint32_t)(r * 128) + kbyte + acb) ^ (((uint32_t)(r & 7)) << 4);
                LDMX4(a[mi], AS + sw);
            }
            uint32_t b[8][2];
#pragma unroll
            for (int ni = 0; ni < 8; ++ni) {
                const int r = brow0 + ni * 8;
                uint32_t sw = ((uint32_t)(r * 128) + kbyte + bcb) ^ (((uint32_t)(r & 7)) << 4);
                LDMX2(b[ni], BS + sw);
            }
#pragma unroll
            for (int mi = 0; mi < 4; ++mi)
#pragma unroll
                for (int ni = 0; ni < 8; ++ni)
                    MMA16816H(c[mi][ni], a[mi], b[ni]);
        }

        if (kc < 3) {
            // A(kc+1) regs -> stage s^1 (nothing reads that region during kc)
            cvtA(s ^ 1, xr);
            __syncthreads();                 // all warps done reading stage s
            if (kc < 2) {
                loadB(s, kc + 2);            // refill just-freed B stage
                loadAreg(kc + 2, xr);
                CP_WAIT(1);                  // B(kc+1) arrived
            } else {
                CP_WAIT(0);
            }
            __syncthreads();
        }
    }

    // ---- epilogue: store z (fp16) + deterministic fused column stats ----
    const int gr = lane >> 2;
    const int qc = (lane & 3) * 2;
    const int mW = rowBase + warp_m * 64;
    const int nW = warp_n * 64;
    const int prow = blockIdx.x * 2 + warp_m;

#pragma unroll
    for (int ni = 0; ni < 8; ++ni) {
        float s0 = 0.f, s1 = 0.f, q0 = 0.f, q1 = 0.f;
        const int n0 = nW + ni * 8 + qc;
#pragma unroll
        for (int mi = 0; mi < 4; ++mi) {
            const float* cf = c[mi][ni];
            const int m0 = mW + mi * 16 + gr;
            *(__half2*)(g_zh + (size_t)m0 * CC + n0)       = __floats2half2_rn(cf[0], cf[1]);
            *(__half2*)(g_zh + (size_t)(m0 + 8) * CC + n0) = __floats2half2_rn(cf[2], cf[3]);
            s0 += cf[0] + cf[2];
            s1 += cf[1] + cf[3];
            q0 += cf[0] * cf[0] + cf[2] * cf[2];
            q1 += cf[1] * cf[1] + cf[3] * cf[3];
        }
#pragma unroll
        for (int off = 4; off < 32; off <<= 1) {
            s0 += __shfl_xor_sync(0xFFFFFFFFu, s0, off);
            s1 += __shfl_xor_sync(0xFFFFFFFFu, s1, off);
            q0 += __shfl_xor_sync(0xFFFFFFFFu, q0, off);
            q1 += __shfl_xor_sync(0xFFFFFFFFu, q1, off);
        }
        if (lane < 4) {
            g_psum[prow * CC + n0]     = s0;
            g_psum[prow * CC + n0 + 1] = s1;
            g_psq [prow * CC + n0]     = q0;
            g_psq [prow * CC + n0 + 1] = q1;
        }
    }
}

// ---------------------------------------------------------------------------
// Kernel 3: finalize LN stats AND fold into per-(b,c) coefficients:
//   ivsc = rsqrt(var+eps)*scale,  bb = bias - mean*ivsc
// grid(4 batches, 8 channel-groups) x 256; coalesced 2-D load + smem tree.
// ---------------------------------------------------------------------------
__global__ void k_finalize(const float* __restrict__ scale,
                           const float* __restrict__ bias) {
    const int b  = blockIdx.x;
    const int cg = blockIdx.y;
    const int tx = threadIdx.x & 31;
    const int ty = threadIdx.x >> 5;      // 0..7
    const int c  = cg * 32 + tx;

    float s = 0.f, s2 = 0.f;
#pragma unroll
    for (int i = 0; i < 8; ++i) {
        const int p = ty * 8 + i;
        s  += g_psum[(b * 64 + p) * CC + c];
        s2 += g_psq [(b * 64 + p) * CC + c];
    }
    __shared__ float rs[8][32], rq[8][32];
    rs[ty][tx] = s;
    rq[ty][tx] = s2;
    __syncthreads();
    if (ty == 0) {
#pragma unroll
        for (int i = 1; i < 8; ++i) { s += rs[i][tx]; s2 += rq[i][tx]; }
        const float mean = s * (1.f / NN);
        const float var  = s2 * (1.f / NN) - mean * mean;
        const float inv  = rsqrtf(var + LN_EPS);
        const float iv_s = inv * scale[c];
        g_ivsc[b * CC + c] = iv_s;
        g_bb  [b * CC + c] = bias[c] - mean * iv_s;
    }
}

// ---------------------------------------------------------------------------
// Kernel 4: epilogue  out = relu(z*ivsc + bb) + x
// Thread = 8 consecutive channels: 1 x uint4 (8 fp16 z) + 2 x float4 X in,
// 2 x float4 out. Coefficients are small per-batch vectors (L1-resident).
// ---------------------------------------------------------------------------
__global__ void __launch_bounds__(256)
k_epi(const float* __restrict__ X, float* __restrict__ out) {
    const int idx = blockIdx.x * blockDim.x + threadIdx.x;   // 8-channel group
    const int cg  = idx & 31;          // group within row (32 x 8 = 256 ch)
    const int b   = idx >> 17;         // (idx>>5)>>12

    const uint4 zp = ((const uint4*)g_zh)[idx];
    const float4 x0 = ((const float4*)X)[idx * 2];
    const float4 x1 = ((const float4*)X)[idx * 2 + 1];
    const float4 s0 = ((const float4*)(g_ivsc + b * CC))[cg * 2];
    const float4 s1 = ((const float4*)(g_ivsc + b * CC))[cg * 2 + 1];
    const float4 b0 = ((const float4*)(g_bb + b * CC))[cg * 2];
    const float4 b1 = ((const float4*)(g_bb + b * CC))[cg * 2 + 1];

    const float2 z01 = __half22float2(*(const __half2*)&zp.x);
    const float2 z23 = __half22float2(*(const __half2*)&zp.y);
    const float2 z45 = __half22float2(*(const __half2*)&zp.z);
    const float2 z67 = __half22float2(*(const __half2*)&zp.w);

    float4 o0, o1;
    o0.x = fmaxf(z01.x * s0.x + b0.x, 0.f) + x0.x;
    o0.y = fmaxf(z01.y * s0.y + b0.y, 0.f) + x0.y;
    o0.z = fmaxf(z23.x * s0.z + b0.z, 0.f) + x0.z;
    o0.w = fmaxf(z23.y * s0.w + b0.w, 0.f) + x0.w;
    o1.x = fmaxf(z45.x * s1.x + b1.x, 0.f) + x1.x;
    o1.y = fmaxf(z45.y * s1.y + b1.y, 0.f) + x1.y;
    o1.z = fmaxf(z67.x * s1.z + b1.z, 0.f) + x1.z;
    o1.w = fmaxf(z67.y * s1.w + b1.w, 0.f) + x1.w;

    ((float4*)out)[idx * 2]     = o0;
    ((float4*)out)[idx * 2 + 1] = o1;
}

// ---------------------------------------------------------------------------
// Inputs: 0=inputs 1=mask 2=Wq 3=bq 4=Wk 5=bk 6=Wv 7=bv 8=Wo 9=bo
//         10=ln_scale 11=ln_bias
// mask/Wq/bq/Wk/bk numerically irrelevant (softmax column-sum collapse);
// bv/bo cancel in the points-axis LayerNorm. All dead.
// ---------------------------------------------------------------------------
extern "C" void kernel_launch(void* const* d_in, const int* in_sizes, int n_in,
                              void* d_out, int out_size) {
    const float* x        = (const float*)d_in[0];
    const float* Wv       = (const float*)d_in[6];
    const float* Wo       = (const float*)d_in[8];
    const float* ln_scale = (const float*)d_in[10];
    const float* ln_bias  = (const float*)d_in[11];
    float* out = (float*)d_out;

    cudaFuncSetAttribute(k_gemm_mma, cudaFuncAttributeMaxDynamicSharedMemorySize, SMEM_TOTAL);

    k_prep<<<CC, CC>>>(Wv, Wo);
    k_gemm_mma<<<M_TOT / 128, 256, SMEM_TOTAL>>>(x);
    k_finalize<<<dim3(BB, 8), 256>>>(ln_scale, ln_bias);
    k_epi<<<(M_TOT * CC / 8) / 256, 256>>>(x, out);
}